// round 1
// baseline (speedup 1.0000x reference)
#include <cuda_runtime.h>
#include <cuda_bf16.h>
#include <cstdint>

// Problem constants
#define SEQL   2048
#define BATCH  2
#define NHEAD  16
#define DHEAD  64
#define DMODEL 1024
#define MTOK   (SEQL * BATCH)   // 4096 tokens

// Scratch (device globals: allocation-free rule)
__device__ float g_q[(size_t)BATCH * NHEAD * SEQL * DHEAD];   // head-major [b][h][s][dh]
__device__ float g_k[(size_t)BATCH * NHEAD * SEQL * DHEAD];
__device__ float g_v[(size_t)BATCH * NHEAD * SEQL * DHEAD];
__device__ float g_ctx[(size_t)MTOK * DMODEL];                // token-major [t][d]

// ---------------------------------------------------------------------------
// SGEMM: C[m][n] = sum_k A[m][k] * W[n][k] + bias[n]
// A: [M, K] row-major, W: [N, K] row-major (i.e. computes A @ W^T + b)
// BM=BN=128, BK=8, 256 threads, 8x8 microtile (split 4+4 fragments).
// HEADMAJOR: scatter C into [b][h][s][dh] layout (for Q/K/V). Else row-major.
// ---------------------------------------------------------------------------
template <bool HEADMAJOR>
__global__ __launch_bounds__(256) void sgemm_nt(
    const float* __restrict__ A, const float* __restrict__ W,
    const float* __restrict__ bias, float* __restrict__ C,
    int M, int N, int K)
{
    __shared__ float As[8][128];
    __shared__ float Bs[8][128];

    const int tid = threadIdx.x;
    const int m0 = blockIdx.y * 128;
    const int n0 = blockIdx.x * 128;
    const int tx = tid & 15;     // 0..15
    const int ty = tid >> 4;     // 0..15

    const int ldRow = tid >> 1;        // 0..127
    const int ldCol = (tid & 1) * 4;   // 0 or 4

    float acc[8][8];
#pragma unroll
    for (int i = 0; i < 8; i++)
#pragma unroll
        for (int j = 0; j < 8; j++) acc[i][j] = 0.f;

    const float* Aptr = A + (size_t)(m0 + ldRow) * K + ldCol;
    const float* Wptr = W + (size_t)(n0 + ldRow) * K + ldCol;

    for (int k0 = 0; k0 < K; k0 += 8) {
        float4 av = *reinterpret_cast<const float4*>(Aptr + k0);
        float4 bv = *reinterpret_cast<const float4*>(Wptr + k0);
        __syncthreads();
        As[ldCol + 0][ldRow] = av.x;
        As[ldCol + 1][ldRow] = av.y;
        As[ldCol + 2][ldRow] = av.z;
        As[ldCol + 3][ldRow] = av.w;
        Bs[ldCol + 0][ldRow] = bv.x;
        Bs[ldCol + 1][ldRow] = bv.y;
        Bs[ldCol + 2][ldRow] = bv.z;
        Bs[ldCol + 3][ldRow] = bv.w;
        __syncthreads();

#pragma unroll
        for (int k = 0; k < 8; k++) {
            float4 a0 = *reinterpret_cast<const float4*>(&As[k][ty * 4]);
            float4 a1 = *reinterpret_cast<const float4*>(&As[k][64 + ty * 4]);
            float4 b0 = *reinterpret_cast<const float4*>(&Bs[k][tx * 4]);
            float4 b1 = *reinterpret_cast<const float4*>(&Bs[k][64 + tx * 4]);
            float af[8] = {a0.x, a0.y, a0.z, a0.w, a1.x, a1.y, a1.z, a1.w};
            float bf[8] = {b0.x, b0.y, b0.z, b0.w, b1.x, b1.y, b1.z, b1.w};
#pragma unroll
            for (int i = 0; i < 8; i++)
#pragma unroll
                for (int j = 0; j < 8; j++)
                    acc[i][j] += af[i] * bf[j];
        }
    }

    // Epilogue
#pragma unroll
    for (int i = 0; i < 8; i++) {
        int gm = m0 + ((i < 4) ? (ty * 4 + i) : (64 + ty * 4 + i - 4));
#pragma unroll
        for (int jh = 0; jh < 2; jh++) {
            int gn = n0 + jh * 64 + tx * 4;
            float4 bb = *reinterpret_cast<const float4*>(bias + gn);
            float4 o;
            o.x = acc[i][jh * 4 + 0] + bb.x;
            o.y = acc[i][jh * 4 + 1] + bb.y;
            o.z = acc[i][jh * 4 + 2] + bb.z;
            o.w = acc[i][jh * 4 + 3] + bb.w;
            if (HEADMAJOR) {
                // token gm = s*BATCH + b ; col gn = h*64 + dh (dh%4==0, within head)
                int s = gm >> 1;            // BATCH = 2
                int b = gm & 1;
                int h = gn >> 6;
                int dh = gn & 63;
                float* dst = C + (((size_t)(b * NHEAD + h) * SEQL + s) * DHEAD + dh);
                *reinterpret_cast<float4*>(dst) = o;
            } else {
                *reinterpret_cast<float4*>(C + (size_t)gm * N + gn) = o;
            }
        }
    }
}

// ---------------------------------------------------------------------------
// Causal flash attention (fp32). One block = 64 queries of one (b,h).
// 64 threads, 1 thread per query row. Q/O/scores in registers.
// K/V tiles of 32 keys staged in shared; all shared reads are warp-broadcast.
// ---------------------------------------------------------------------------
__global__ __launch_bounds__(64) void attn_kernel(
    const float* __restrict__ gq, const float* __restrict__ gk,
    const float* __restrict__ gv, float* __restrict__ ctx)
{
    const int qt = blockIdx.x;          // query tile (64 queries)
    const int bh = blockIdx.y;          // b*NHEAD + h
    const int b  = bh / NHEAD;
    const int h  = bh % NHEAD;
    const int tid = threadIdx.x;        // 0..63
    const int qi  = qt * 64 + tid;      // global query index

    const float* Qb = gq + ((size_t)bh * SEQL + (size_t)qt * 64) * DHEAD;
    const float* Kb = gk + (size_t)bh * SEQL * DHEAD;
    const float* Vb = gv + (size_t)bh * SEQL * DHEAD;

    __shared__ float Ksh[32 * 64];
    __shared__ float Vsh[32 * 64];

    const float scale = 0.125f;  // 1/sqrt(64)

    float Qr[64];
#pragma unroll
    for (int d = 0; d < 64; d += 4) {
        float4 v = *reinterpret_cast<const float4*>(Qb + (size_t)tid * 64 + d);
        Qr[d + 0] = v.x * scale;
        Qr[d + 1] = v.y * scale;
        Qr[d + 2] = v.z * scale;
        Qr[d + 3] = v.w * scale;
    }

    float O[64];
#pragma unroll
    for (int d = 0; d < 64; d++) O[d] = 0.f;
    float m = -1e30f;
    float l = 0.f;

    const int nkt = 2 * qt + 2;  // key tiles of 32 covering keys <= qt*64+63

    for (int kt = 0; kt < nkt; kt++) {
        __syncthreads();
        // cooperative load of 32x64 K and V tiles (coalesced float4)
        const float4* Kg = reinterpret_cast<const float4*>(Kb + (size_t)kt * 32 * 64);
        const float4* Vg = reinterpret_cast<const float4*>(Vb + (size_t)kt * 32 * 64);
        float4* Ks4 = reinterpret_cast<float4*>(Ksh);
        float4* Vs4 = reinterpret_cast<float4*>(Vsh);
#pragma unroll
        for (int r = 0; r < 8; r++) {
            int f = r * 64 + tid;
            Ks4[f] = Kg[f];
            Vs4[f] = Vg[f];
        }
        __syncthreads();

        const int j0 = kt * 32;
        float Sc[32];
#pragma unroll
        for (int j = 0; j < 32; j++) {
            float s0 = 0.f, s1 = 0.f, s2 = 0.f, s3 = 0.f;
#pragma unroll
            for (int d = 0; d < 64; d += 4) {
                float4 kv = *reinterpret_cast<const float4*>(Ksh + j * 64 + d);
                s0 += Qr[d + 0] * kv.x;
                s1 += Qr[d + 1] * kv.y;
                s2 += Qr[d + 2] * kv.z;
                s3 += Qr[d + 3] * kv.w;
            }
            float s = (s0 + s1) + (s2 + s3);
            Sc[j] = (j0 + j <= qi) ? s : -1e30f;
        }

        float mt = m;
#pragma unroll
        for (int j = 0; j < 32; j++) mt = fmaxf(mt, Sc[j]);

        float corr = __expf(m - mt);
        m = mt;
        l *= corr;
#pragma unroll
        for (int d = 0; d < 64; d++) O[d] *= corr;

#pragma unroll
        for (int j = 0; j < 32; j++) {
            float p = __expf(Sc[j] - m);
            l += p;
#pragma unroll
            for (int d = 0; d < 64; d += 4) {
                float4 vv = *reinterpret_cast<const float4*>(Vsh + j * 64 + d);
                O[d + 0] += p * vv.x;
                O[d + 1] += p * vv.y;
                O[d + 2] += p * vv.z;
                O[d + 3] += p * vv.w;
            }
        }
    }

    const float inv = 1.f / l;
    float* dst = ctx + ((size_t)qi * BATCH + b) * DMODEL + h * DHEAD;
#pragma unroll
    for (int d = 0; d < 64; d += 4) {
        float4 o;
        o.x = O[d + 0] * inv;
        o.y = O[d + 1] * inv;
        o.z = O[d + 2] * inv;
        o.w = O[d + 3] * inv;
        *reinterpret_cast<float4*>(dst + d) = o;
    }
}

// ---------------------------------------------------------------------------
// Launch
// Inputs: 0 query, 1 q_w, 2 q_b, 3 k_w, 4 k_b, 5 v_w, 6 v_b, 7 out_w,
//         8 out_b, 9 attn_mask (causal; reproduced analytically)
// ---------------------------------------------------------------------------
extern "C" void kernel_launch(void* const* d_in, const int* in_sizes, int n_in,
                              void* d_out, int out_size)
{
    const float* query = (const float*)d_in[0];
    const float* q_w   = (const float*)d_in[1];
    const float* q_b   = (const float*)d_in[2];
    const float* k_w   = (const float*)d_in[3];
    const float* k_b   = (const float*)d_in[4];
    const float* v_w   = (const float*)d_in[5];
    const float* v_b   = (const float*)d_in[6];
    const float* out_w = (const float*)d_in[7];
    const float* out_b = (const float*)d_in[8];
    float* out = (float*)d_out;

    float *qp, *kp, *vp, *cp;
    cudaGetSymbolAddress((void**)&qp, g_q);
    cudaGetSymbolAddress((void**)&kp, g_k);
    cudaGetSymbolAddress((void**)&vp, g_v);
    cudaGetSymbolAddress((void**)&cp, g_ctx);

    dim3 gproj(DMODEL / 128, MTOK / 128);   // (8, 32)
    sgemm_nt<true><<<gproj, 256>>>(query, q_w, q_b, qp, MTOK, DMODEL, DMODEL);
    sgemm_nt<true><<<gproj, 256>>>(query, k_w, k_b, kp, MTOK, DMODEL, DMODEL);
    sgemm_nt<true><<<gproj, 256>>>(query, v_w, v_b, vp, MTOK, DMODEL, DMODEL);

    dim3 gattn(SEQL / 64, BATCH * NHEAD);   // (32, 32)
    attn_kernel<<<gattn, 64>>>(qp, kp, vp, cp);

    sgemm_nt<false><<<gproj, 256>>>(cp, out_w, out_b, out, MTOK, DMODEL, DMODEL);
}

// round 3
// speedup vs baseline: 1.2324x; 1.2324x over previous
#include <cuda_runtime.h>
#include <cuda_bf16.h>
#include <cstdint>

// Problem constants
#define SEQL   2048
#define BATCH  2
#define NHEAD  16
#define DHEAD  64
#define DMODEL 1024
#define MTOK   (SEQL * BATCH)   // 4096 tokens

// ---------------------------------------------------------------------------
// Scratch (device globals: allocation-free rule)
// ---------------------------------------------------------------------------
__device__ float g_q[(size_t)BATCH * NHEAD * SEQL * DHEAD];   // [b][h][s][dh]
__device__ float g_k[(size_t)BATCH * NHEAD * SEQL * DHEAD];
__device__ float g_v[(size_t)BATCH * NHEAD * SEQL * DHEAD];
__device__ float g_ctx[(size_t)MTOK * DMODEL];                // [t][d]

// bf16 split buffers (hi/lo)
__device__ __nv_bfloat16 g_x_hi[(size_t)MTOK * DMODEL];
__device__ __nv_bfloat16 g_x_lo[(size_t)MTOK * DMODEL];
__device__ __nv_bfloat16 g_c_hi[(size_t)MTOK * DMODEL];
__device__ __nv_bfloat16 g_c_lo[(size_t)MTOK * DMODEL];
__device__ __nv_bfloat16 g_qw_hi[(size_t)DMODEL * DMODEL];
__device__ __nv_bfloat16 g_qw_lo[(size_t)DMODEL * DMODEL];
__device__ __nv_bfloat16 g_kw_hi[(size_t)DMODEL * DMODEL];
__device__ __nv_bfloat16 g_kw_lo[(size_t)DMODEL * DMODEL];
__device__ __nv_bfloat16 g_vw_hi[(size_t)DMODEL * DMODEL];
__device__ __nv_bfloat16 g_vw_lo[(size_t)DMODEL * DMODEL];
__device__ __nv_bfloat16 g_ow_hi[(size_t)DMODEL * DMODEL];
__device__ __nv_bfloat16 g_ow_lo[(size_t)DMODEL * DMODEL];

// ---------------------------------------------------------------------------
// mma.sync / ldmatrix helpers (standard PTX, no sm_103a-gated features)
// ---------------------------------------------------------------------------
__device__ __forceinline__ uint32_t smem_u32(const void* p) {
    uint32_t a;
    asm("{ .reg .u64 t; cvta.to.shared.u64 t, %1; cvt.u32.u64 %0, t; }"
        : "=r"(a) : "l"(p));
    return a;
}

__device__ __forceinline__ void ldm_x4(uint32_t* r, uint32_t addr) {
    asm volatile("ldmatrix.sync.aligned.m8n8.x4.shared.b16 {%0,%1,%2,%3}, [%4];"
                 : "=r"(r[0]), "=r"(r[1]), "=r"(r[2]), "=r"(r[3])
                 : "r"(addr));
}

__device__ __forceinline__ void mma_bf16(float* d, const uint32_t* a,
                                         uint32_t b0, uint32_t b1) {
    asm volatile(
        "mma.sync.aligned.m16n8k16.row.col.f32.bf16.bf16.f32 "
        "{%0,%1,%2,%3}, {%4,%5,%6,%7}, {%8,%9}, {%0,%1,%2,%3};"
        : "+f"(d[0]), "+f"(d[1]), "+f"(d[2]), "+f"(d[3])
        : "r"(a[0]), "r"(a[1]), "r"(a[2]), "r"(a[3]), "r"(b0), "r"(b1));
}

// ---------------------------------------------------------------------------
// fp32 -> (bf16 hi, bf16 lo) split conversion
// ---------------------------------------------------------------------------
__global__ __launch_bounds__(256) void cvt_split(
    const float* __restrict__ x, __nv_bfloat16* __restrict__ hi,
    __nv_bfloat16* __restrict__ lo, int n)
{
    int i = (blockIdx.x * 256 + threadIdx.x) * 4;
    if (i >= n) return;
    float4 v = *reinterpret_cast<const float4*>(x + i);
    __nv_bfloat16 h0 = __float2bfloat16(v.x);
    __nv_bfloat16 h1 = __float2bfloat16(v.y);
    __nv_bfloat16 h2 = __float2bfloat16(v.z);
    __nv_bfloat16 h3 = __float2bfloat16(v.w);
    __nv_bfloat16 l0 = __float2bfloat16(v.x - __bfloat162float(h0));
    __nv_bfloat16 l1 = __float2bfloat16(v.y - __bfloat162float(h1));
    __nv_bfloat16 l2 = __float2bfloat16(v.z - __bfloat162float(h2));
    __nv_bfloat16 l3 = __float2bfloat16(v.w - __bfloat162float(h3));
    __nv_bfloat162* ph = reinterpret_cast<__nv_bfloat162*>(hi + i);
    __nv_bfloat162* pl = reinterpret_cast<__nv_bfloat162*>(lo + i);
    ph[0] = __nv_bfloat162(h0, h1);
    ph[1] = __nv_bfloat162(h2, h3);
    pl[0] = __nv_bfloat162(l0, l1);
    pl[1] = __nv_bfloat162(l2, l3);
}

// ---------------------------------------------------------------------------
// Tensor-core GEMM via mma.sync (bf16 hi/lo compensated, fp32 accumulate)
// C[m][n] = sum_k A[m][k]*W[n][k] + bias[n]
// CTA 128x128, BK=32, 8 warps (2x4), warp tile 64x32.
// ---------------------------------------------------------------------------
#define AST 40   // smem row stride in bf16 elems (80B: conflict-free ldmatrix)

template <bool HEADMAJOR>
__global__ __launch_bounds__(256, 1)
void gemm_mma(const __nv_bfloat16* __restrict__ Ahi, const __nv_bfloat16* __restrict__ Alo,
              const __nv_bfloat16* __restrict__ Bhi, const __nv_bfloat16* __restrict__ Blo,
              const float* __restrict__ bias, float* __restrict__ C,
              int M, int N, int K)
{
    __shared__ __nv_bfloat16 sAh[128 * AST];
    __shared__ __nv_bfloat16 sAl[128 * AST];
    __shared__ __nv_bfloat16 sBh[128 * AST];
    __shared__ __nv_bfloat16 sBl[128 * AST];

    const int tid = threadIdx.x;
    const int wid = tid >> 5;
    const int lid = tid & 31;
    const int wr = wid >> 2;         // 0..1 : 64-row strip
    const int wc = wid & 3;          // 0..3 : 32-col strip

    const int m0 = blockIdx.y * 128;
    const int n0 = blockIdx.x * 128;

    float acc[4][4][4];
#pragma unroll
    for (int i = 0; i < 4; i++)
#pragma unroll
        for (int j = 0; j < 4; j++)
#pragma unroll
            for (int e = 0; e < 4; e++) acc[i][j][e] = 0.f;

    // ldmatrix lane address components
    const int aRow = lid & 15;                 // row within 16
    const int aCol = (lid >> 4) << 3;          // 0 or 8
    const int bRow = (lid & 7) + ((lid & 16) >> 1);   // n within 16
    const int bCol = ((lid >> 3) & 1) << 3;    // 0 or 8

    const uint32_t sAh_u = smem_u32(sAh);
    const uint32_t sAl_u = smem_u32(sAl);
    const uint32_t sBh_u = smem_u32(sBh);
    const uint32_t sBl_u = smem_u32(sBl);

    const int nIter = K >> 5;   // K/32
    for (int it = 0; it < nIter; it++) {
        const int kc = it << 5;

        // ---- global -> reg prefetch (2 x 16B chunks per array per thread)
        uint4 vAh[2], vAl[2], vBh[2], vBl[2];
#pragma unroll
        for (int i = 0; i < 2; i++) {
            int chunk = tid + i * 256;       // 0..511
            int row = chunk >> 2;
            int c8 = (chunk & 3) * 8;
            size_t offA = (size_t)(m0 + row) * K + kc + c8;
            size_t offB = (size_t)(n0 + row) * K + kc + c8;
            vAh[i] = *reinterpret_cast<const uint4*>(Ahi + offA);
            vAl[i] = *reinterpret_cast<const uint4*>(Alo + offA);
            vBh[i] = *reinterpret_cast<const uint4*>(Bhi + offB);
            vBl[i] = *reinterpret_cast<const uint4*>(Blo + offB);
        }
        __syncthreads();
#pragma unroll
        for (int i = 0; i < 2; i++) {
            int chunk = tid + i * 256;
            int row = chunk >> 2;
            int c8 = (chunk & 3) * 8;
            int so = row * AST + c8;
            *reinterpret_cast<uint4*>(sAh + so) = vAh[i];
            *reinterpret_cast<uint4*>(sAl + so) = vAl[i];
            *reinterpret_cast<uint4*>(sBh + so) = vBh[i];
            *reinterpret_cast<uint4*>(sBl + so) = vBl[i];
        }
        __syncthreads();

        // ---- compute: two k16 steps
#pragma unroll
        for (int ks = 0; ks < 32; ks += 16) {
            uint32_t ah[4][4], al[4][4];
#pragma unroll
            for (int mi = 0; mi < 4; mi++) {
                uint32_t off = ((wr * 64 + mi * 16 + aRow) * AST + ks + aCol) * 2;
                ldm_x4(ah[mi], sAh_u + off);
                ldm_x4(al[mi], sAl_u + off);
            }
            uint32_t bh[2][4], bl[2][4];
#pragma unroll
            for (int p = 0; p < 2; p++) {
                uint32_t off = ((wc * 32 + p * 16 + bRow) * AST + ks + bCol) * 2;
                ldm_x4(bh[p], sBh_u + off);
                ldm_x4(bl[p], sBl_u + off);
            }
#pragma unroll
            for (int mi = 0; mi < 4; mi++)
#pragma unroll
                for (int p = 0; p < 2; p++)
#pragma unroll
                    for (int s = 0; s < 2; s++) {
                        float* d = acc[mi][p * 2 + s];
                        mma_bf16(d, ah[mi], bh[p][s * 2], bh[p][s * 2 + 1]);
                        mma_bf16(d, ah[mi], bl[p][s * 2], bl[p][s * 2 + 1]);
                        mma_bf16(d, al[mi], bh[p][s * 2], bh[p][s * 2 + 1]);
                    }
        }
    }

    // ---- epilogue: bias add + store (fp32)
    const int tq = lid >> 2;       // t/4 : row within 8
    const int tr = (lid & 3) * 2;  // col pair
#pragma unroll
    for (int mi = 0; mi < 4; mi++) {
#pragma unroll
        for (int ni = 0; ni < 4; ni++) {
            int gm = m0 + wr * 64 + mi * 16 + tq;
            int gn = n0 + wc * 32 + ni * 8 + tr;
            float2 bb = *reinterpret_cast<const float2*>(bias + gn);
#pragma unroll
            for (int half = 0; half < 2; half++) {
                int row = gm + half * 8;
                float2 o;
                o.x = acc[mi][ni][half * 2 + 0] + bb.x;
                o.y = acc[mi][ni][half * 2 + 1] + bb.y;
                if (HEADMAJOR) {
                    int s = row >> 1;          // BATCH = 2
                    int b = row & 1;
                    int h = gn >> 6;
                    int dh = gn & 63;
                    float* dst = C + (((size_t)(b * NHEAD + h) * SEQL + s) * DHEAD + dh);
                    *reinterpret_cast<float2*>(dst) = o;
                } else {
                    *reinterpret_cast<float2*>(C + (size_t)row * N + gn) = o;
                }
            }
        }
    }
}

// ---------------------------------------------------------------------------
// Causal flash attention (fp32). One block = 64 queries of one (b,h).
// ---------------------------------------------------------------------------
__global__ __launch_bounds__(64) void attn_kernel(
    const float* __restrict__ gq, const float* __restrict__ gk,
    const float* __restrict__ gv, float* __restrict__ ctx)
{
    const int qt = blockIdx.x;
    const int bh = blockIdx.y;
    const int b  = bh / NHEAD;
    const int h  = bh % NHEAD;
    const int tid = threadIdx.x;
    const int qi  = qt * 64 + tid;

    const float* Qb = gq + ((size_t)bh * SEQL + (size_t)qt * 64) * DHEAD;
    const float* Kb = gk + (size_t)bh * SEQL * DHEAD;
    const float* Vb = gv + (size_t)bh * SEQL * DHEAD;

    __shared__ float Ksh[32 * 64];
    __shared__ float Vsh[32 * 64];

    const float scale = 0.125f;

    float Qr[64];
#pragma unroll
    for (int d = 0; d < 64; d += 4) {
        float4 v = *reinterpret_cast<const float4*>(Qb + (size_t)tid * 64 + d);
        Qr[d + 0] = v.x * scale;
        Qr[d + 1] = v.y * scale;
        Qr[d + 2] = v.z * scale;
        Qr[d + 3] = v.w * scale;
    }

    float O[64];
#pragma unroll
    for (int d = 0; d < 64; d++) O[d] = 0.f;
    float m = -1e30f;
    float l = 0.f;

    const int nkt = 2 * qt + 2;

    for (int kt = 0; kt < nkt; kt++) {
        __syncthreads();
        const float4* Kg = reinterpret_cast<const float4*>(Kb + (size_t)kt * 32 * 64);
        const float4* Vg = reinterpret_cast<const float4*>(Vb + (size_t)kt * 32 * 64);
        float4* Ks4 = reinterpret_cast<float4*>(Ksh);
        float4* Vs4 = reinterpret_cast<float4*>(Vsh);
#pragma unroll
        for (int r = 0; r < 8; r++) {
            int f = r * 64 + tid;
            Ks4[f] = Kg[f];
            Vs4[f] = Vg[f];
        }
        __syncthreads();

        const int j0 = kt * 32;
        float Sc[32];
#pragma unroll
        for (int j = 0; j < 32; j++) {
            float s0 = 0.f, s1 = 0.f, s2 = 0.f, s3 = 0.f;
#pragma unroll
            for (int d = 0; d < 64; d += 4) {
                float4 kv = *reinterpret_cast<const float4*>(Ksh + j * 64 + d);
                s0 += Qr[d + 0] * kv.x;
                s1 += Qr[d + 1] * kv.y;
                s2 += Qr[d + 2] * kv.z;
                s3 += Qr[d + 3] * kv.w;
            }
            float s = (s0 + s1) + (s2 + s3);
            Sc[j] = (j0 + j <= qi) ? s : -1e30f;
        }

        float mt = m;
#pragma unroll
        for (int j = 0; j < 32; j++) mt = fmaxf(mt, Sc[j]);

        float corr = __expf(m - mt);
        m = mt;
        l *= corr;
#pragma unroll
        for (int d = 0; d < 64; d++) O[d] *= corr;

#pragma unroll
        for (int j = 0; j < 32; j++) {
            float p = __expf(Sc[j] - m);
            l += p;
#pragma unroll
            for (int d = 0; d < 64; d += 4) {
                float4 vv = *reinterpret_cast<const float4*>(Vsh + j * 64 + d);
                O[d + 0] += p * vv.x;
                O[d + 1] += p * vv.y;
                O[d + 2] += p * vv.z;
                O[d + 3] += p * vv.w;
            }
        }
    }

    const float inv = 1.f / l;
    float* dst = ctx + ((size_t)qi * BATCH + b) * DMODEL + h * DHEAD;
#pragma unroll
    for (int d = 0; d < 64; d += 4) {
        float4 o;
        o.x = O[d + 0] * inv;
        o.y = O[d + 1] * inv;
        o.z = O[d + 2] * inv;
        o.w = O[d + 3] * inv;
        *reinterpret_cast<float4*>(dst + d) = o;
    }
}

// ---------------------------------------------------------------------------
// Launch
// ---------------------------------------------------------------------------
extern "C" void kernel_launch(void* const* d_in, const int* in_sizes, int n_in,
                              void* d_out, int out_size)
{
    const float* query = (const float*)d_in[0];
    const float* q_w   = (const float*)d_in[1];
    const float* q_b   = (const float*)d_in[2];
    const float* k_w   = (const float*)d_in[3];
    const float* k_b   = (const float*)d_in[4];
    const float* v_w   = (const float*)d_in[5];
    const float* v_b   = (const float*)d_in[6];
    const float* out_w = (const float*)d_in[7];
    const float* out_b = (const float*)d_in[8];
    float* out = (float*)d_out;

    float *qp, *kp, *vp, *cp;
    cudaGetSymbolAddress((void**)&qp, g_q);
    cudaGetSymbolAddress((void**)&kp, g_k);
    cudaGetSymbolAddress((void**)&vp, g_v);
    cudaGetSymbolAddress((void**)&cp, g_ctx);

    __nv_bfloat16 *xh, *xl, *ch, *cl, *qwh, *qwl, *kwh, *kwl, *vwh, *vwl, *owh, *owl;
    cudaGetSymbolAddress((void**)&xh, g_x_hi);
    cudaGetSymbolAddress((void**)&xl, g_x_lo);
    cudaGetSymbolAddress((void**)&ch, g_c_hi);
    cudaGetSymbolAddress((void**)&cl, g_c_lo);
    cudaGetSymbolAddress((void**)&qwh, g_qw_hi);
    cudaGetSymbolAddress((void**)&qwl, g_qw_lo);
    cudaGetSymbolAddress((void**)&kwh, g_kw_hi);
    cudaGetSymbolAddress((void**)&kwl, g_kw_lo);
    cudaGetSymbolAddress((void**)&vwh, g_vw_hi);
    cudaGetSymbolAddress((void**)&vwl, g_vw_lo);
    cudaGetSymbolAddress((void**)&owh, g_ow_hi);
    cudaGetSymbolAddress((void**)&owl, g_ow_lo);

    const int nTok = MTOK * DMODEL;      // 4M
    const int nW   = DMODEL * DMODEL;    // 1M

    cvt_split<<<nTok / 1024, 256>>>(query, xh, xl, nTok);
    cvt_split<<<nW / 1024, 256>>>(q_w, qwh, qwl, nW);
    cvt_split<<<nW / 1024, 256>>>(k_w, kwh, kwl, nW);
    cvt_split<<<nW / 1024, 256>>>(v_w, vwh, vwl, nW);
    cvt_split<<<nW / 1024, 256>>>(out_w, owh, owl, nW);

    dim3 gproj(DMODEL / 128, MTOK / 128);   // (8, 32)
    gemm_mma<true><<<gproj, 256>>>(xh, xl, qwh, qwl, q_b, qp, MTOK, DMODEL, DMODEL);
    gemm_mma<true><<<gproj, 256>>>(xh, xl, kwh, kwl, k_b, kp, MTOK, DMODEL, DMODEL);
    gemm_mma<true><<<gproj, 256>>>(xh, xl, vwh, vwl, v_b, vp, MTOK, DMODEL, DMODEL);

    dim3 gattn(SEQL / 64, BATCH * NHEAD);   // (32, 32)
    attn_kernel<<<gattn, 64>>>(qp, kp, vp, cp);

    cvt_split<<<nTok / 1024, 256>>>(cp, ch, cl, nTok);
    gemm_mma<false><<<gproj, 256>>>(ch, cl, owh, owl, out_b, out, MTOK, DMODEL, DMODEL);
}

// round 5
// speedup vs baseline: 3.0782x; 2.4979x over previous
#include <cuda_runtime.h>
#include <cuda_bf16.h>
#include <cstdint>

// Problem constants
#define SEQL   2048
#define BATCH  2
#define NHEAD  16
#define DHEAD  64
#define DMODEL 1024
#define MTOK   (SEQL * BATCH)   // 4096 tokens
#define NBH    (BATCH * NHEAD)  // 32

// ---------------------------------------------------------------------------
// Scratch (device globals: allocation-free rule)
// ---------------------------------------------------------------------------
__device__ __nv_bfloat16 g_x_hi[(size_t)MTOK * DMODEL];
__device__ __nv_bfloat16 g_x_lo[(size_t)MTOK * DMODEL];
__device__ __nv_bfloat16 g_c_hi[(size_t)MTOK * DMODEL];
__device__ __nv_bfloat16 g_c_lo[(size_t)MTOK * DMODEL];
__device__ __nv_bfloat16 g_qw_hi[(size_t)DMODEL * DMODEL];
__device__ __nv_bfloat16 g_qw_lo[(size_t)DMODEL * DMODEL];
__device__ __nv_bfloat16 g_kw_hi[(size_t)DMODEL * DMODEL];
__device__ __nv_bfloat16 g_kw_lo[(size_t)DMODEL * DMODEL];
__device__ __nv_bfloat16 g_vw_hi[(size_t)DMODEL * DMODEL];
__device__ __nv_bfloat16 g_vw_lo[(size_t)DMODEL * DMODEL];
__device__ __nv_bfloat16 g_ow_hi[(size_t)DMODEL * DMODEL];
__device__ __nv_bfloat16 g_ow_lo[(size_t)DMODEL * DMODEL];
// Q/K/V head-major [bh][s][dh], hi/lo
__device__ __nv_bfloat16 g_qh[(size_t)NBH * SEQL * DHEAD];
__device__ __nv_bfloat16 g_ql[(size_t)NBH * SEQL * DHEAD];
__device__ __nv_bfloat16 g_kh[(size_t)NBH * SEQL * DHEAD];
__device__ __nv_bfloat16 g_kl[(size_t)NBH * SEQL * DHEAD];
__device__ __nv_bfloat16 g_vh[(size_t)NBH * SEQL * DHEAD];
__device__ __nv_bfloat16 g_vl[(size_t)NBH * SEQL * DHEAD];

// ---------------------------------------------------------------------------
// mma.sync / ldmatrix helpers
// ---------------------------------------------------------------------------
__device__ __forceinline__ uint32_t smem_u32(const void* p) {
    uint32_t a;
    asm("{ .reg .u64 t; cvta.to.shared.u64 t, %1; cvt.u32.u64 %0, t; }"
        : "=r"(a) : "l"(p));
    return a;
}

__device__ __forceinline__ void ldm_x4(uint32_t* r, uint32_t addr) {
    asm volatile("ldmatrix.sync.aligned.m8n8.x4.shared.b16 {%0,%1,%2,%3}, [%4];"
                 : "=r"(r[0]), "=r"(r[1]), "=r"(r[2]), "=r"(r[3])
                 : "r"(addr));
}

__device__ __forceinline__ void ldm_x4_t(uint32_t* r, uint32_t addr) {
    asm volatile("ldmatrix.sync.aligned.m8n8.x4.trans.shared.b16 {%0,%1,%2,%3}, [%4];"
                 : "=r"(r[0]), "=r"(r[1]), "=r"(r[2]), "=r"(r[3])
                 : "r"(addr));
}

__device__ __forceinline__ void mma_bf16(float* d, const uint32_t* a,
                                         uint32_t b0, uint32_t b1) {
    asm volatile(
        "mma.sync.aligned.m16n8k16.row.col.f32.bf16.bf16.f32 "
        "{%0,%1,%2,%3}, {%4,%5,%6,%7}, {%8,%9}, {%0,%1,%2,%3};"
        : "+f"(d[0]), "+f"(d[1]), "+f"(d[2]), "+f"(d[3])
        : "r"(a[0]), "r"(a[1]), "r"(a[2]), "r"(a[3]), "r"(b0), "r"(b1));
}

__device__ __forceinline__ uint32_t pack2(float a, float b) {
    __nv_bfloat162 t = __floats2bfloat162_rn(a, b);
    return *reinterpret_cast<uint32_t*>(&t);
}

__device__ __forceinline__ void split2(float a, float b, uint32_t& hi, uint32_t& lo) {
    __nv_bfloat16 ha = __float2bfloat16(a);
    __nv_bfloat16 hb = __float2bfloat16(b);
    hi = pack2(__bfloat162float(ha), __bfloat162float(hb));  // exact re-pack
    lo = pack2(a - __bfloat162float(ha), b - __bfloat162float(hb));
}

// ---------------------------------------------------------------------------
// fp32 -> (bf16 hi, bf16 lo) split conversion with optional scale
// ---------------------------------------------------------------------------
__global__ __launch_bounds__(256) void cvt_split(
    const float* __restrict__ x, __nv_bfloat16* __restrict__ hi,
    __nv_bfloat16* __restrict__ lo, int n, float scale)
{
    int i = (blockIdx.x * 256 + threadIdx.x) * 4;
    if (i >= n) return;
    float4 v = *reinterpret_cast<const float4*>(x + i);
    v.x *= scale; v.y *= scale; v.z *= scale; v.w *= scale;
    uint32_t h0, l0, h1, l1;
    split2(v.x, v.y, h0, l0);
    split2(v.z, v.w, h1, l1);
    uint32_t* ph = reinterpret_cast<uint32_t*>(hi + i);
    uint32_t* pl = reinterpret_cast<uint32_t*>(lo + i);
    ph[0] = h0; ph[1] = h1;
    pl[0] = l0; pl[1] = l1;
}

// ---------------------------------------------------------------------------
// Tensor-core GEMM (bf16 hi/lo compensated, fp32 accumulate)
// C[m][n] = sum_k A[m][k]*W[n][k] + bias[n]*bscale
// MODE 0: fp32 row-major C. MODE 1: bf16 hi/lo split, head-major scatter.
// ---------------------------------------------------------------------------
#define AST 40

template <int MODE>
__global__ __launch_bounds__(256, 1)
void gemm_mma(const __nv_bfloat16* __restrict__ Ahi, const __nv_bfloat16* __restrict__ Alo,
              const __nv_bfloat16* __restrict__ Bhi, const __nv_bfloat16* __restrict__ Blo,
              const float* __restrict__ bias, float bscale,
              float* __restrict__ C,
              __nv_bfloat16* __restrict__ Chi, __nv_bfloat16* __restrict__ Clo,
              int M, int N, int K)
{
    __shared__ __nv_bfloat16 sAh[128 * AST];
    __shared__ __nv_bfloat16 sAl[128 * AST];
    __shared__ __nv_bfloat16 sBh[128 * AST];
    __shared__ __nv_bfloat16 sBl[128 * AST];

    const int tid = threadIdx.x;
    const int wid = tid >> 5;
    const int lid = tid & 31;
    const int wr = wid >> 2;
    const int wc = wid & 3;

    const int m0 = blockIdx.y * 128;
    const int n0 = blockIdx.x * 128;

    float acc[4][4][4];
#pragma unroll
    for (int i = 0; i < 4; i++)
#pragma unroll
        for (int j = 0; j < 4; j++)
#pragma unroll
            for (int e = 0; e < 4; e++) acc[i][j][e] = 0.f;

    const int aRow = lid & 15;
    const int aCol = (lid >> 4) << 3;
    const int bRow = (lid & 7) + ((lid & 16) >> 1);
    const int bCol = ((lid >> 3) & 1) << 3;

    const uint32_t sAh_u = smem_u32(sAh);
    const uint32_t sAl_u = smem_u32(sAl);
    const uint32_t sBh_u = smem_u32(sBh);
    const uint32_t sBl_u = smem_u32(sBl);

    const int nIter = K >> 5;
    for (int it = 0; it < nIter; it++) {
        const int kc = it << 5;
        uint4 vAh[2], vAl[2], vBh[2], vBl[2];
#pragma unroll
        for (int i = 0; i < 2; i++) {
            int chunk = tid + i * 256;
            int row = chunk >> 2;
            int c8 = (chunk & 3) * 8;
            size_t offA = (size_t)(m0 + row) * K + kc + c8;
            size_t offB = (size_t)(n0 + row) * K + kc + c8;
            vAh[i] = *reinterpret_cast<const uint4*>(Ahi + offA);
            vAl[i] = *reinterpret_cast<const uint4*>(Alo + offA);
            vBh[i] = *reinterpret_cast<const uint4*>(Bhi + offB);
            vBl[i] = *reinterpret_cast<const uint4*>(Blo + offB);
        }
        __syncthreads();
#pragma unroll
        for (int i = 0; i < 2; i++) {
            int chunk = tid + i * 256;
            int row = chunk >> 2;
            int c8 = (chunk & 3) * 8;
            int so = row * AST + c8;
            *reinterpret_cast<uint4*>(sAh + so) = vAh[i];
            *reinterpret_cast<uint4*>(sAl + so) = vAl[i];
            *reinterpret_cast<uint4*>(sBh + so) = vBh[i];
            *reinterpret_cast<uint4*>(sBl + so) = vBl[i];
        }
        __syncthreads();

#pragma unroll
        for (int ks = 0; ks < 32; ks += 16) {
            uint32_t ah[4][4], al[4][4];
#pragma unroll
            for (int mi = 0; mi < 4; mi++) {
                uint32_t off = ((wr * 64 + mi * 16 + aRow) * AST + ks + aCol) * 2;
                ldm_x4(ah[mi], sAh_u + off);
                ldm_x4(al[mi], sAl_u + off);
            }
            uint32_t bh[2][4], bl[2][4];
#pragma unroll
            for (int p = 0; p < 2; p++) {
                uint32_t off = ((wc * 32 + p * 16 + bRow) * AST + ks + bCol) * 2;
                ldm_x4(bh[p], sBh_u + off);
                ldm_x4(bl[p], sBl_u + off);
            }
#pragma unroll
            for (int mi = 0; mi < 4; mi++)
#pragma unroll
                for (int p = 0; p < 2; p++)
#pragma unroll
                    for (int s = 0; s < 2; s++) {
                        float* d = acc[mi][p * 2 + s];
                        mma_bf16(d, ah[mi], bh[p][s * 2], bh[p][s * 2 + 1]);
                        mma_bf16(d, ah[mi], bl[p][s * 2], bl[p][s * 2 + 1]);
                        mma_bf16(d, al[mi], bh[p][s * 2], bh[p][s * 2 + 1]);
                    }
        }
    }

    // Epilogue
    const int tq = lid >> 2;
    const int tr = (lid & 3) * 2;
#pragma unroll
    for (int mi = 0; mi < 4; mi++) {
#pragma unroll
        for (int ni = 0; ni < 4; ni++) {
            int gm = m0 + wr * 64 + mi * 16 + tq;
            int gn = n0 + wc * 32 + ni * 8 + tr;
            float2 bb = *reinterpret_cast<const float2*>(bias + gn);
#pragma unroll
            for (int half = 0; half < 2; half++) {
                int row = gm + half * 8;
                float ox = acc[mi][ni][half * 2 + 0] + bb.x * bscale;
                float oy = acc[mi][ni][half * 2 + 1] + bb.y * bscale;
                if (MODE == 1) {
                    // head-major bf16 split: token row -> (b, s), col -> (h, dh)
                    int s = row >> 1;
                    int b = row & 1;
                    int h = gn >> 6;
                    int dh = gn & 63;
                    size_t di = (((size_t)(b * NHEAD + h) * SEQL + s) * DHEAD + dh);
                    uint32_t hi, lo;
                    split2(ox, oy, hi, lo);
                    *reinterpret_cast<uint32_t*>(Chi + di) = hi;
                    *reinterpret_cast<uint32_t*>(Clo + di) = lo;
                } else {
                    float2 o; o.x = ox; o.y = oy;
                    *reinterpret_cast<float2*>(C + (size_t)row * N + gn) = o;
                }
            }
        }
    }
}

// ---------------------------------------------------------------------------
// Tensor-core causal flash attention.
// Block: 128 threads (4 warps), 64 queries of one (b,h). Tiles 64 keys.
// Q pre-scaled by 1/8 (folded into W_q). Emits ctx as bf16 hi/lo.
// ---------------------------------------------------------------------------
#define KST 72   // smem row stride (elems): 144B rows, 16B aligned

__global__ __launch_bounds__(128, 2) void attn_mma(
    const __nv_bfloat16* __restrict__ qh, const __nv_bfloat16* __restrict__ ql,
    const __nv_bfloat16* __restrict__ kh, const __nv_bfloat16* __restrict__ kl,
    const __nv_bfloat16* __restrict__ vh, const __nv_bfloat16* __restrict__ vl,
    __nv_bfloat16* __restrict__ ch, __nv_bfloat16* __restrict__ cl)
{
    __shared__ __nv_bfloat16 sKh[64 * KST];
    __shared__ __nv_bfloat16 sKl[64 * KST];
    __shared__ __nv_bfloat16 sVh[64 * KST];
    __shared__ __nv_bfloat16 sVl[64 * KST];

    const int qt  = (int)(gridDim.x - 1) - (int)blockIdx.x;  // long blocks first
    const int bh  = blockIdx.y;
    const int tid = threadIdx.x;
    const int wq  = tid >> 5;
    const int lid = tid & 31;

    const size_t headoff = (size_t)bh * SEQL * DHEAD;
    const uint32_t sKh_u = smem_u32(sKh);
    const uint32_t sKl_u = smem_u32(sKl);
    const uint32_t sVh_u = smem_u32(sVh);
    const uint32_t sVl_u = smem_u32(sVl);

    // ---- stage Q tile (reuse K buffers), load persistent Q fragments
    {
        const __nv_bfloat16* Qh = qh + headoff + (size_t)qt * 64 * DHEAD;
        const __nv_bfloat16* Ql = ql + headoff + (size_t)qt * 64 * DHEAD;
#pragma unroll
        for (int i = tid; i < 512; i += 128) {
            int row = i >> 3, c8 = (i & 7) * 8;
            *reinterpret_cast<uint4*>(sKh + row * KST + c8) =
                *reinterpret_cast<const uint4*>(Qh + row * 64 + c8);
            *reinterpret_cast<uint4*>(sKl + row * KST + c8) =
                *reinterpret_cast<const uint4*>(Ql + row * 64 + c8);
        }
    }
    __syncthreads();

    const int aRow = lid & 15;
    const int aCol = (lid >> 4) << 3;
    uint32_t qfh[4][4], qfl[4][4];
#pragma unroll
    for (int ks = 0; ks < 4; ks++) {
        uint32_t off = ((wq * 16 + aRow) * KST + ks * 16 + aCol) * 2;
        ldm_x4(qfh[ks], sKh_u + off);
        ldm_x4(qfl[ks], sKl_u + off);
    }

    float O[8][4];
#pragma unroll
    for (int i = 0; i < 8; i++)
#pragma unroll
        for (int e = 0; e < 4; e++) O[i][e] = 0.f;
    float m0 = -1e30f, m1 = -1e30f, l0 = 0.f, l1 = 0.f;

    const int bRow = (lid & 7) + ((lid & 16) >> 1);
    const int bCol = ((lid >> 3) & 1) << 3;
    const int r0 = wq * 16 + (lid >> 2);   // local query row (and +8)

    for (int kt = 0; kt <= qt; kt++) {
        __syncthreads();   // previous iteration's smem reads done
        const size_t koff = headoff + (size_t)kt * 64 * DHEAD;
#pragma unroll
        for (int i = tid; i < 512; i += 128) {
            int row = i >> 3, c8 = (i & 7) * 8;
            int so = row * KST + c8;
            size_t go = koff + row * 64 + c8;
            *reinterpret_cast<uint4*>(sKh + so) = *reinterpret_cast<const uint4*>(kh + go);
            *reinterpret_cast<uint4*>(sKl + so) = *reinterpret_cast<const uint4*>(kl + go);
            *reinterpret_cast<uint4*>(sVh + so) = *reinterpret_cast<const uint4*>(vh + go);
            *reinterpret_cast<uint4*>(sVl + so) = *reinterpret_cast<const uint4*>(vl + go);
        }
        __syncthreads();

        // ---- S = Q K^T (compensated)
        float S[8][4];
#pragma unroll
        for (int i = 0; i < 8; i++)
#pragma unroll
            for (int e = 0; e < 4; e++) S[i][e] = 0.f;
#pragma unroll
        for (int ks = 0; ks < 4; ks++) {
#pragma unroll
            for (int ng = 0; ng < 4; ng++) {
                uint32_t kfh[4], kfl[4];
                uint32_t off = ((ng * 16 + bRow) * KST + ks * 16 + bCol) * 2;
                ldm_x4(kfh, sKh_u + off);
                ldm_x4(kfl, sKl_u + off);
#pragma unroll
                for (int s = 0; s < 2; s++) {
                    float* d = S[ng * 2 + s];
                    mma_bf16(d, qfh[ks], kfh[s * 2], kfh[s * 2 + 1]);
                    mma_bf16(d, qfh[ks], kfl[s * 2], kfl[s * 2 + 1]);
                    mma_bf16(d, qfl[ks], kfh[s * 2], kfh[s * 2 + 1]);
                }
            }
        }

        // ---- causal mask (diagonal tile only)
        if (kt == qt) {
#pragma unroll
            for (int ni = 0; ni < 8; ni++) {
                int c = ni * 8 + (lid & 3) * 2;
                if (c > r0)     S[ni][0] = -1e30f;
                if (c + 1 > r0) S[ni][1] = -1e30f;
                if (c > r0 + 8)     S[ni][2] = -1e30f;
                if (c + 1 > r0 + 8) S[ni][3] = -1e30f;
            }
        }

        // ---- online softmax
        float mx0 = -1e30f, mx1 = -1e30f;
#pragma unroll
        for (int ni = 0; ni < 8; ni++) {
            mx0 = fmaxf(mx0, fmaxf(S[ni][0], S[ni][1]));
            mx1 = fmaxf(mx1, fmaxf(S[ni][2], S[ni][3]));
        }
        mx0 = fmaxf(mx0, __shfl_xor_sync(0xffffffffu, mx0, 1));
        mx0 = fmaxf(mx0, __shfl_xor_sync(0xffffffffu, mx0, 2));
        mx1 = fmaxf(mx1, __shfl_xor_sync(0xffffffffu, mx1, 1));
        mx1 = fmaxf(mx1, __shfl_xor_sync(0xffffffffu, mx1, 2));
        float mn0 = fmaxf(m0, mx0), mn1 = fmaxf(m1, mx1);
        float c0 = __expf(m0 - mn0), c1 = __expf(m1 - mn1);
        m0 = mn0; m1 = mn1;

        uint32_t pA_hi[8], pA_lo[8], pB_hi[8], pB_lo[8];
        float s0 = 0.f, s1 = 0.f;
#pragma unroll
        for (int ni = 0; ni < 8; ni++) {
            float p0 = __expf(S[ni][0] - m0);
            float p1 = __expf(S[ni][1] - m0);
            float p2 = __expf(S[ni][2] - m1);
            float p3 = __expf(S[ni][3] - m1);
            s0 += p0 + p1;
            s1 += p2 + p3;
            split2(p0, p1, pA_hi[ni], pA_lo[ni]);
            split2(p2, p3, pB_hi[ni], pB_lo[ni]);
        }
        s0 += __shfl_xor_sync(0xffffffffu, s0, 1);
        s0 += __shfl_xor_sync(0xffffffffu, s0, 2);
        s1 += __shfl_xor_sync(0xffffffffu, s1, 1);
        s1 += __shfl_xor_sync(0xffffffffu, s1, 2);
        l0 = l0 * c0 + s0;
        l1 = l1 * c1 + s1;
#pragma unroll
        for (int ni = 0; ni < 8; ni++) {
            O[ni][0] *= c0; O[ni][1] *= c0;
            O[ni][2] *= c1; O[ni][3] *= c1;
        }

        // ---- O += P V (compensated; V fragments via ldmatrix.trans)
#pragma unroll
        for (int ks = 0; ks < 4; ks++) {        // key chunks of 16
            uint32_t aH[4] = {pA_hi[2 * ks], pB_hi[2 * ks], pA_hi[2 * ks + 1], pB_hi[2 * ks + 1]};
            uint32_t aL[4] = {pA_lo[2 * ks], pB_lo[2 * ks], pA_lo[2 * ks + 1], pB_lo[2 * ks + 1]};
#pragma unroll
            for (int ng = 0; ng < 4; ng++) {    // dh groups of 16
                uint32_t vfh[4], vfl[4];
                uint32_t off = ((ks * 16 + (lid & 15)) * KST + ng * 16 + ((lid >> 4) << 3)) * 2;
                ldm_x4_t(vfh, sVh_u + off);
                ldm_x4_t(vfl, sVl_u + off);
#pragma unroll
                for (int s = 0; s < 2; s++) {
                    float* d = O[ng * 2 + s];
                    mma_bf16(d, aH, vfh[s * 2], vfh[s * 2 + 1]);
                    mma_bf16(d, aH, vfl[s * 2], vfl[s * 2 + 1]);
                    mma_bf16(d, aL, vfh[s * 2], vfh[s * 2 + 1]);
                }
            }
        }
    }

    // ---- epilogue: normalize, split to bf16 hi/lo, scatter to ctx [t][d]
    const float inv0 = 1.f / l0;
    const float inv1 = 1.f / l1;
    const int b = bh >> 4;           // bh = b*NHEAD + h
    const int h = bh & 15;
    const int sq = qt * 64 + wq * 16 + (lid >> 2);
#pragma unroll
    for (int ni = 0; ni < 8; ni++) {
        int col = h * 64 + ni * 8 + (lid & 3) * 2;
        uint32_t hi, lo;
        // row sq
        split2(O[ni][0] * inv0, O[ni][1] * inv0, hi, lo);
        size_t d0 = (size_t)(sq * BATCH + b) * DMODEL + col;
        *reinterpret_cast<uint32_t*>(ch + d0) = hi;
        *reinterpret_cast<uint32_t*>(cl + d0) = lo;
        // row sq + 8
        split2(O[ni][2] * inv1, O[ni][3] * inv1, hi, lo);
        size_t d1 = (size_t)((sq + 8) * BATCH + b) * DMODEL + col;
        *reinterpret_cast<uint32_t*>(ch + d1) = hi;
        *reinterpret_cast<uint32_t*>(cl + d1) = lo;
    }
}

// ---------------------------------------------------------------------------
// Launch
// ---------------------------------------------------------------------------
extern "C" void kernel_launch(void* const* d_in, const int* in_sizes, int n_in,
                              void* d_out, int out_size)
{
    const float* query = (const float*)d_in[0];
    const float* q_w   = (const float*)d_in[1];
    const float* q_b   = (const float*)d_in[2];
    const float* k_w   = (const float*)d_in[3];
    const float* k_b   = (const float*)d_in[4];
    const float* v_w   = (const float*)d_in[5];
    const float* v_b   = (const float*)d_in[6];
    const float* out_w = (const float*)d_in[7];
    const float* out_b = (const float*)d_in[8];
    float* out = (float*)d_out;

    __nv_bfloat16 *xh, *xl, *ch, *cl;
    __nv_bfloat16 *qwh, *qwl, *kwh, *kwl, *vwh, *vwl, *owh, *owl;
    __nv_bfloat16 *qhp, *qlp, *khp, *klp, *vhp, *vlp;
    cudaGetSymbolAddress((void**)&xh, g_x_hi);
    cudaGetSymbolAddress((void**)&xl, g_x_lo);
    cudaGetSymbolAddress((void**)&ch, g_c_hi);
    cudaGetSymbolAddress((void**)&cl, g_c_lo);
    cudaGetSymbolAddress((void**)&qwh, g_qw_hi);
    cudaGetSymbolAddress((void**)&qwl, g_qw_lo);
    cudaGetSymbolAddress((void**)&kwh, g_kw_hi);
    cudaGetSymbolAddress((void**)&kwl, g_kw_lo);
    cudaGetSymbolAddress((void**)&vwh, g_vw_hi);
    cudaGetSymbolAddress((void**)&vwl, g_vw_lo);
    cudaGetSymbolAddress((void**)&owh, g_ow_hi);
    cudaGetSymbolAddress((void**)&owl, g_ow_lo);
    cudaGetSymbolAddress((void**)&qhp, g_qh);
    cudaGetSymbolAddress((void**)&qlp, g_ql);
    cudaGetSymbolAddress((void**)&khp, g_kh);
    cudaGetSymbolAddress((void**)&klp, g_kl);
    cudaGetSymbolAddress((void**)&vhp, g_vh);
    cudaGetSymbolAddress((void**)&vlp, g_vl);

    const int nTok = MTOK * DMODEL;      // 4M
    const int nW   = DMODEL * DMODEL;    // 1M
    const float qscale = 0.125f;         // 1/sqrt(64), folded into W_q and q_b

    cvt_split<<<nTok / 1024, 256>>>(query, xh, xl, nTok, 1.0f);
    cvt_split<<<nW / 1024, 256>>>(q_w, qwh, qwl, nW, qscale);
    cvt_split<<<nW / 1024, 256>>>(k_w, kwh, kwl, nW, 1.0f);
    cvt_split<<<nW / 1024, 256>>>(v_w, vwh, vwl, nW, 1.0f);
    cvt_split<<<nW / 1024, 256>>>(out_w, owh, owl, nW, 1.0f);

    dim3 gproj(DMODEL / 128, MTOK / 128);   // (8, 32)
    gemm_mma<1><<<gproj, 256>>>(xh, xl, qwh, qwl, q_b, qscale, nullptr, qhp, qlp,
                                MTOK, DMODEL, DMODEL);
    gemm_mma<1><<<gproj, 256>>>(xh, xl, kwh, kwl, k_b, 1.0f, nullptr, khp, klp,
                                MTOK, DMODEL, DMODEL);
    gemm_mma<1><<<gproj, 256>>>(xh, xl, vwh, vwl, v_b, 1.0f, nullptr, vhp, vlp,
                                MTOK, DMODEL, DMODEL);

    dim3 gattn(SEQL / 64, NBH);             // (32, 32)
    attn_mma<<<gattn, 128>>>(qhp, qlp, khp, klp, vhp, vlp, ch, cl);

    gemm_mma<0><<<gproj, 256>>>(ch, cl, owh, owl, out_b, 1.0f, out, nullptr, nullptr,
                                MTOK, DMODEL, DMODEL);
}

// round 7
// speedup vs baseline: 3.5151x; 1.1419x over previous
#include <cuda_runtime.h>
#include <cuda_bf16.h>
#include <cstdint>

// Problem constants
#define SEQL   2048
#define BATCH  2
#define NHEAD  16
#define DHEAD  64
#define DMODEL 1024
#define MTOK   (SEQL * BATCH)   // 4096 tokens
#define NBH    (BATCH * NHEAD)  // 32

// ---------------------------------------------------------------------------
// Scratch (device globals: allocation-free rule)
// ---------------------------------------------------------------------------
__device__ __nv_bfloat16 g_x_hi[(size_t)MTOK * DMODEL];
__device__ __nv_bfloat16 g_x_lo[(size_t)MTOK * DMODEL];
__device__ __nv_bfloat16 g_c_hi[(size_t)MTOK * DMODEL];
__device__ __nv_bfloat16 g_c_lo[(size_t)MTOK * DMODEL];
__device__ __nv_bfloat16 g_qw_hi[(size_t)DMODEL * DMODEL];
__device__ __nv_bfloat16 g_qw_lo[(size_t)DMODEL * DMODEL];
__device__ __nv_bfloat16 g_kw_hi[(size_t)DMODEL * DMODEL];
__device__ __nv_bfloat16 g_kw_lo[(size_t)DMODEL * DMODEL];
__device__ __nv_bfloat16 g_vw_hi[(size_t)DMODEL * DMODEL];
__device__ __nv_bfloat16 g_vw_lo[(size_t)DMODEL * DMODEL];
__device__ __nv_bfloat16 g_ow_hi[(size_t)DMODEL * DMODEL];
__device__ __nv_bfloat16 g_ow_lo[(size_t)DMODEL * DMODEL];
__device__ __nv_bfloat16 g_qh[(size_t)NBH * SEQL * DHEAD];
__device__ __nv_bfloat16 g_ql[(size_t)NBH * SEQL * DHEAD];
__device__ __nv_bfloat16 g_kh[(size_t)NBH * SEQL * DHEAD];
__device__ __nv_bfloat16 g_kl[(size_t)NBH * SEQL * DHEAD];
__device__ __nv_bfloat16 g_vh[(size_t)NBH * SEQL * DHEAD];
__device__ __nv_bfloat16 g_vl[(size_t)NBH * SEQL * DHEAD];

// ---------------------------------------------------------------------------
// PTX helpers
// ---------------------------------------------------------------------------
__device__ __forceinline__ uint32_t smem_u32(const void* p) {
    uint32_t a;
    asm("{ .reg .u64 t; cvta.to.shared.u64 t, %1; cvt.u32.u64 %0, t; }"
        : "=r"(a) : "l"(p));
    return a;
}

__device__ __forceinline__ void cp16(uint32_t s, const void* g) {
    asm volatile("cp.async.cg.shared.global [%0], [%1], 16;" :: "r"(s), "l"(g));
}
__device__ __forceinline__ void cp_commit() {
    asm volatile("cp.async.commit_group;" ::: "memory");
}
template <int N>
__device__ __forceinline__ void cp_wait() {
    asm volatile("cp.async.wait_group %0;" :: "n"(N) : "memory");
}

__device__ __forceinline__ void ldm_x4(uint32_t* r, uint32_t addr) {
    asm volatile("ldmatrix.sync.aligned.m8n8.x4.shared.b16 {%0,%1,%2,%3}, [%4];"
                 : "=r"(r[0]), "=r"(r[1]), "=r"(r[2]), "=r"(r[3])
                 : "r"(addr));
}
__device__ __forceinline__ void ldm_x4_t(uint32_t* r, uint32_t addr) {
    asm volatile("ldmatrix.sync.aligned.m8n8.x4.trans.shared.b16 {%0,%1,%2,%3}, [%4];"
                 : "=r"(r[0]), "=r"(r[1]), "=r"(r[2]), "=r"(r[3])
                 : "r"(addr));
}
__device__ __forceinline__ void mma_bf16(float* d, const uint32_t* a,
                                         uint32_t b0, uint32_t b1) {
    asm volatile(
        "mma.sync.aligned.m16n8k16.row.col.f32.bf16.bf16.f32 "
        "{%0,%1,%2,%3}, {%4,%5,%6,%7}, {%8,%9}, {%0,%1,%2,%3};"
        : "+f"(d[0]), "+f"(d[1]), "+f"(d[2]), "+f"(d[3])
        : "r"(a[0]), "r"(a[1]), "r"(a[2]), "r"(a[3]), "r"(b0), "r"(b1));
}

__device__ __forceinline__ uint32_t pack2(float a, float b) {
    __nv_bfloat162 t = __floats2bfloat162_rn(a, b);
    return *reinterpret_cast<uint32_t*>(&t);
}
__device__ __forceinline__ void split2(float a, float b, uint32_t& hi, uint32_t& lo) {
    __nv_bfloat16 ha = __float2bfloat16(a);
    __nv_bfloat16 hb = __float2bfloat16(b);
    hi = pack2(__bfloat162float(ha), __bfloat162float(hb));
    lo = pack2(a - __bfloat162float(ha), b - __bfloat162float(hb));
}

// ---------------------------------------------------------------------------
// fp32 -> (bf16 hi, bf16 lo)
// ---------------------------------------------------------------------------
__global__ __launch_bounds__(256) void cvt_split(
    const float* __restrict__ x, __nv_bfloat16* __restrict__ hi,
    __nv_bfloat16* __restrict__ lo, int n, float scale)
{
    int i = (blockIdx.x * 256 + threadIdx.x) * 4;
    if (i >= n) return;
    float4 v = *reinterpret_cast<const float4*>(x + i);
    v.x *= scale; v.y *= scale; v.z *= scale; v.w *= scale;
    uint32_t h0, l0, h1, l1;
    split2(v.x, v.y, h0, l0);
    split2(v.z, v.w, h1, l1);
    uint32_t* ph = reinterpret_cast<uint32_t*>(hi + i);
    uint32_t* pl = reinterpret_cast<uint32_t*>(lo + i);
    ph[0] = h0; ph[1] = h1;
    pl[0] = l0; pl[1] = l1;
}

// ---------------------------------------------------------------------------
// GEMM core: 128x128 CTA tile, BK=32, 8 warps, cp.async 2-stage pipeline.
// ---------------------------------------------------------------------------
#define AST    40
#define G_ARR  10240                    // 128*AST*2 bytes per array
#define G_STG  (4 * G_ARR)              // bytes per stage
#define G_SMEM (2 * G_STG)              // 81920

struct ProjSet {
    const __nv_bfloat16 *Bh, *Bl;
    const float* bias;
    float bscale;
    __nv_bfloat16 *Ch, *Cl;
};

__device__ __forceinline__ void gemm_issue(
    uint32_t sbase, int st,
    const __nv_bfloat16* Ahi, const __nv_bfloat16* Alo,
    const __nv_bfloat16* Bhi, const __nv_bfloat16* Blo,
    int m0, int n0, int kc, int K, int tid)
{
    uint32_t b = sbase + st * G_STG;
#pragma unroll
    for (int i = 0; i < 2; i++) {
        int chunk = tid + i * 256;
        int row = chunk >> 2;
        int c8 = (chunk & 3) * 8;
        uint32_t so = (uint32_t)(row * AST + c8) * 2;
        size_t offA = (size_t)(m0 + row) * K + kc + c8;
        size_t offB = (size_t)(n0 + row) * K + kc + c8;
        cp16(b + so,              Ahi + offA);
        cp16(b + G_ARR + so,      Alo + offA);
        cp16(b + 2 * G_ARR + so,  Bhi + offB);
        cp16(b + 3 * G_ARR + so,  Blo + offB);
    }
}

__device__ __forceinline__ void gemm_core(
    uint32_t sbase,
    const __nv_bfloat16* Ahi, const __nv_bfloat16* Alo,
    const __nv_bfloat16* Bhi, const __nv_bfloat16* Blo,
    int m0, int n0, int K, int tid, float acc[4][4][4])
{
    const int wid = tid >> 5;
    const int lid = tid & 31;
    const int wr = wid >> 2;
    const int wc = wid & 3;
    const int aRow = lid & 15;
    const int aCol = (lid >> 4) << 3;
    const int bRow = (lid & 7) + ((lid & 16) >> 1);
    const int bCol = ((lid >> 3) & 1) << 3;

    const int nIter = K >> 5;
    gemm_issue(sbase, 0, Ahi, Alo, Bhi, Blo, m0, n0, 0, K, tid);
    cp_commit();

    for (int it = 0; it < nIter; it++) {
        if (it + 1 < nIter) {
            gemm_issue(sbase, (it + 1) & 1, Ahi, Alo, Bhi, Blo,
                       m0, n0, (it + 1) << 5, K, tid);
            cp_commit();
            cp_wait<1>();
        } else {
            cp_wait<0>();
        }
        __syncthreads();

        const uint32_t bA_h = sbase + (it & 1) * G_STG;
        const uint32_t bA_l = bA_h + G_ARR;
        const uint32_t bB_h = bA_h + 2 * G_ARR;
        const uint32_t bB_l = bA_h + 3 * G_ARR;

#pragma unroll
        for (int ks = 0; ks < 32; ks += 16) {
            uint32_t ah[4][4], al[4][4];
#pragma unroll
            for (int mi = 0; mi < 4; mi++) {
                uint32_t off = (uint32_t)((wr * 64 + mi * 16 + aRow) * AST + ks + aCol) * 2;
                ldm_x4(ah[mi], bA_h + off);
                ldm_x4(al[mi], bA_l + off);
            }
            uint32_t bh[2][4], bl[2][4];
#pragma unroll
            for (int p = 0; p < 2; p++) {
                uint32_t off = (uint32_t)((wc * 32 + p * 16 + bRow) * AST + ks + bCol) * 2;
                ldm_x4(bh[p], bB_h + off);
                ldm_x4(bl[p], bB_l + off);
            }
#pragma unroll
            for (int mi = 0; mi < 4; mi++)
#pragma unroll
                for (int p = 0; p < 2; p++)
#pragma unroll
                    for (int s = 0; s < 2; s++) {
                        float* d = acc[mi][p * 2 + s];
                        mma_bf16(d, ah[mi], bh[p][s * 2], bh[p][s * 2 + 1]);
                        mma_bf16(d, ah[mi], bl[p][s * 2], bl[p][s * 2 + 1]);
                        mma_bf16(d, al[mi], bh[p][s * 2], bh[p][s * 2 + 1]);
                    }
        }
        __syncthreads();
    }
}

// Fused Q/K/V projection: grid (N/128, M/128, 3)
__global__ __launch_bounds__(256, 1)
void gemm_qkv(const __nv_bfloat16* __restrict__ Ahi, const __nv_bfloat16* __restrict__ Alo,
              ProjSet p0, ProjSet p1, ProjSet p2, int M, int N, int K)
{
    extern __shared__ char smem[];
    const uint32_t sbase = smem_u32(smem);
    const int tid = threadIdx.x;
    const ProjSet P = (blockIdx.z == 0) ? p0 : (blockIdx.z == 1) ? p1 : p2;

    const int m0 = blockIdx.y * 128;
    const int n0 = blockIdx.x * 128;

    float acc[4][4][4];
#pragma unroll
    for (int i = 0; i < 4; i++)
#pragma unroll
        for (int j = 0; j < 4; j++)
#pragma unroll
            for (int e = 0; e < 4; e++) acc[i][j][e] = 0.f;

    gemm_core(sbase, Ahi, Alo, P.Bh, P.Bl, m0, n0, K, tid, acc);

    const int wid = tid >> 5;
    const int lid = tid & 31;
    const int wr = wid >> 2;
    const int wc = wid & 3;
    const int tq = lid >> 2;
    const int tr = (lid & 3) * 2;
#pragma unroll
    for (int mi = 0; mi < 4; mi++) {
#pragma unroll
        for (int ni = 0; ni < 4; ni++) {
            int gm = m0 + wr * 64 + mi * 16 + tq;
            int gn = n0 + wc * 32 + ni * 8 + tr;
            float2 bb = *reinterpret_cast<const float2*>(P.bias + gn);
#pragma unroll
            for (int half = 0; half < 2; half++) {
                int row = gm + half * 8;
                float ox = acc[mi][ni][half * 2 + 0] + bb.x * P.bscale;
                float oy = acc[mi][ni][half * 2 + 1] + bb.y * P.bscale;
                int s = row >> 1;
                int b = row & 1;
                int h = gn >> 6;
                int dh = gn & 63;
                size_t di = (((size_t)(b * NHEAD + h) * SEQL + s) * DHEAD + dh);
                uint32_t hi, lo;
                split2(ox, oy, hi, lo);
                *reinterpret_cast<uint32_t*>(P.Ch + di) = hi;
                *reinterpret_cast<uint32_t*>(P.Cl + di) = lo;
            }
        }
    }
}

// Output projection: fp32 row-major C
__global__ __launch_bounds__(256, 1)
void gemm_out(const __nv_bfloat16* __restrict__ Ahi, const __nv_bfloat16* __restrict__ Alo,
              const __nv_bfloat16* __restrict__ Bhi, const __nv_bfloat16* __restrict__ Blo,
              const float* __restrict__ bias, float* __restrict__ C,
              int M, int N, int K)
{
    extern __shared__ char smem[];
    const uint32_t sbase = smem_u32(smem);
    const int tid = threadIdx.x;

    const int m0 = blockIdx.y * 128;
    const int n0 = blockIdx.x * 128;

    float acc[4][4][4];
#pragma unroll
    for (int i = 0; i < 4; i++)
#pragma unroll
        for (int j = 0; j < 4; j++)
#pragma unroll
            for (int e = 0; e < 4; e++) acc[i][j][e] = 0.f;

    gemm_core(sbase, Ahi, Alo, Bhi, Blo, m0, n0, K, tid, acc);

    const int wid = tid >> 5;
    const int lid = tid & 31;
    const int wr = wid >> 2;
    const int wc = wid & 3;
    const int tq = lid >> 2;
    const int tr = (lid & 3) * 2;
#pragma unroll
    for (int mi = 0; mi < 4; mi++) {
#pragma unroll
        for (int ni = 0; ni < 4; ni++) {
            int gm = m0 + wr * 64 + mi * 16 + tq;
            int gn = n0 + wc * 32 + ni * 8 + tr;
            float2 bb = *reinterpret_cast<const float2*>(bias + gn);
#pragma unroll
            for (int half = 0; half < 2; half++) {
                int row = gm + half * 8;
                float2 o;
                o.x = acc[mi][ni][half * 2 + 0] + bb.x;
                o.y = acc[mi][ni][half * 2 + 1] + bb.y;
                *reinterpret_cast<float2*>(C + (size_t)row * N + gn) = o;
            }
        }
    }
}

// ---------------------------------------------------------------------------
// Tensor-core causal flash attention, cp.async 2-stage K/V pipeline.
// Block: 128 threads (4 warps), 64 queries of one (b,h). Key tile 64.
// ---------------------------------------------------------------------------
#define KST    72
#define A_ARR  9216                     // 64*KST*2 bytes per array
#define A_STG  (4 * A_ARR)              // bytes per stage
#define A_SMEM (2 * A_STG)              // 73728

__device__ __forceinline__ void attn_issue(
    uint32_t sbase, int st,
    const __nv_bfloat16* kh, const __nv_bfloat16* kl,
    const __nv_bfloat16* vh, const __nv_bfloat16* vl,
    size_t koff, int tid)
{
    uint32_t b = sbase + st * A_STG;
#pragma unroll
    for (int i = tid; i < 512; i += 128) {
        int row = i >> 3, c8 = (i & 7) * 8;
        uint32_t so = (uint32_t)(row * KST + c8) * 2;
        size_t go = koff + row * 64 + c8;
        cp16(b + so,             kh + go);
        cp16(b + A_ARR + so,     kl + go);
        cp16(b + 2 * A_ARR + so, vh + go);
        cp16(b + 3 * A_ARR + so, vl + go);
    }
}

__global__ __launch_bounds__(128, 2) void attn_mma(
    const __nv_bfloat16* __restrict__ qh, const __nv_bfloat16* __restrict__ ql,
    const __nv_bfloat16* __restrict__ kh, const __nv_bfloat16* __restrict__ kl,
    const __nv_bfloat16* __restrict__ vh, const __nv_bfloat16* __restrict__ vl,
    __nv_bfloat16* __restrict__ ch, __nv_bfloat16* __restrict__ cl)
{
    extern __shared__ char smem[];
    const uint32_t sbase = smem_u32(smem);

    const int qt  = (int)(gridDim.x - 1) - (int)blockIdx.x;  // long blocks first
    const int bh  = blockIdx.y;
    const int tid = threadIdx.x;
    const int wq  = tid >> 5;
    const int lid = tid & 31;

    const size_t headoff = (size_t)bh * SEQL * DHEAD;

    // ---- stage Q tile into stage-0 K buffers, load persistent fragments
    {
        const __nv_bfloat16* Qh = qh + headoff + (size_t)qt * 64 * DHEAD;
        const __nv_bfloat16* Ql = ql + headoff + (size_t)qt * 64 * DHEAD;
#pragma unroll
        for (int i = tid; i < 512; i += 128) {
            int row = i >> 3, c8 = (i & 7) * 8;
            uint32_t so = (uint32_t)(row * KST + c8) * 2;
            *reinterpret_cast<uint4*>(smem + so) =
                *reinterpret_cast<const uint4*>(Qh + row * 64 + c8);
            *reinterpret_cast<uint4*>(smem + A_ARR + so) =
                *reinterpret_cast<const uint4*>(Ql + row * 64 + c8);
        }
    }
    __syncthreads();

    const int aRow = lid & 15;
    const int aCol = (lid >> 4) << 3;
    uint32_t qfh[4][4], qfl[4][4];
#pragma unroll
    for (int ks = 0; ks < 4; ks++) {
        uint32_t off = (uint32_t)((wq * 16 + aRow) * KST + ks * 16 + aCol) * 2;
        ldm_x4(qfh[ks], sbase + off);
        ldm_x4(qfl[ks], sbase + A_ARR + off);
    }
    __syncthreads();   // all Q fragments read before stage-0 is overwritten

    attn_issue(sbase, 0, kh, kl, vh, vl, headoff, tid);
    cp_commit();

    float O[8][4];
#pragma unroll
    for (int i = 0; i < 8; i++)
#pragma unroll
        for (int e = 0; e < 4; e++) O[i][e] = 0.f;
    float m0 = -1e30f, m1 = -1e30f, l0 = 0.f, l1 = 0.f;

    const int bRow = (lid & 7) + ((lid & 16) >> 1);
    const int bCol = ((lid >> 3) & 1) << 3;
    const int r0 = wq * 16 + (lid >> 2);

    for (int kt = 0; kt <= qt; kt++) {
        if (kt < qt) {
            attn_issue(sbase, (kt + 1) & 1, kh, kl, vh, vl,
                       headoff + (size_t)(kt + 1) * 64 * DHEAD, tid);
            cp_commit();
            cp_wait<1>();
        } else {
            cp_wait<0>();
        }
        __syncthreads();

        const uint32_t bK_h = sbase + (kt & 1) * A_STG;
        const uint32_t bK_l = bK_h + A_ARR;
        const uint32_t bV_h = bK_h + 2 * A_ARR;
        const uint32_t bV_l = bK_h + 3 * A_ARR;

        // ---- S = Q K^T (compensated)
        float S[8][4];
#pragma unroll
        for (int i = 0; i < 8; i++)
#pragma unroll
            for (int e = 0; e < 4; e++) S[i][e] = 0.f;
#pragma unroll
        for (int ks = 0; ks < 4; ks++) {
#pragma unroll
            for (int ng = 0; ng < 4; ng++) {
                uint32_t kfh[4], kfl[4];
                uint32_t off = (uint32_t)((ng * 16 + bRow) * KST + ks * 16 + bCol) * 2;
                ldm_x4(kfh, bK_h + off);
                ldm_x4(kfl, bK_l + off);
#pragma unroll
                for (int s = 0; s < 2; s++) {
                    float* d = S[ng * 2 + s];
                    mma_bf16(d, qfh[ks], kfh[s * 2], kfh[s * 2 + 1]);
                    mma_bf16(d, qfh[ks], kfl[s * 2], kfl[s * 2 + 1]);
                    mma_bf16(d, qfl[ks], kfh[s * 2], kfh[s * 2 + 1]);
                }
            }
        }

        // ---- causal mask (diagonal tile)
        if (kt == qt) {
#pragma unroll
            for (int ni = 0; ni < 8; ni++) {
                int c = ni * 8 + (lid & 3) * 2;
                if (c > r0)         S[ni][0] = -1e30f;
                if (c + 1 > r0)     S[ni][1] = -1e30f;
                if (c > r0 + 8)     S[ni][2] = -1e30f;
                if (c + 1 > r0 + 8) S[ni][3] = -1e30f;
            }
        }

        // ---- online softmax
        float mx0 = -1e30f, mx1 = -1e30f;
#pragma unroll
        for (int ni = 0; ni < 8; ni++) {
            mx0 = fmaxf(mx0, fmaxf(S[ni][0], S[ni][1]));
            mx1 = fmaxf(mx1, fmaxf(S[ni][2], S[ni][3]));
        }
        mx0 = fmaxf(mx0, __shfl_xor_sync(0xffffffffu, mx0, 1));
        mx0 = fmaxf(mx0, __shfl_xor_sync(0xffffffffu, mx0, 2));
        mx1 = fmaxf(mx1, __shfl_xor_sync(0xffffffffu, mx1, 1));
        mx1 = fmaxf(mx1, __shfl_xor_sync(0xffffffffu, mx1, 2));
        float mn0 = fmaxf(m0, mx0), mn1 = fmaxf(m1, mx1);
        float c0 = __expf(m0 - mn0), c1 = __expf(m1 - mn1);
        m0 = mn0; m1 = mn1;

        uint32_t pA_hi[8], pA_lo[8], pB_hi[8], pB_lo[8];
        float s0 = 0.f, s1 = 0.f;
#pragma unroll
        for (int ni = 0; ni < 8; ni++) {
            float p0 = __expf(S[ni][0] - m0);
            float p1 = __expf(S[ni][1] - m0);
            float p2 = __expf(S[ni][2] - m1);
            float p3 = __expf(S[ni][3] - m1);
            s0 += p0 + p1;
            s1 += p2 + p3;
            split2(p0, p1, pA_hi[ni], pA_lo[ni]);
            split2(p2, p3, pB_hi[ni], pB_lo[ni]);
        }
        s0 += __shfl_xor_sync(0xffffffffu, s0, 1);
        s0 += __shfl_xor_sync(0xffffffffu, s0, 2);
        s1 += __shfl_xor_sync(0xffffffffu, s1, 1);
        s1 += __shfl_xor_sync(0xffffffffu, s1, 2);
        l0 = l0 * c0 + s0;
        l1 = l1 * c1 + s1;
#pragma unroll
        for (int ni = 0; ni < 8; ni++) {
            O[ni][0] *= c0; O[ni][1] *= c0;
            O[ni][2] *= c1; O[ni][3] *= c1;
        }

        // ---- O += P V (compensated)
#pragma unroll
        for (int ks = 0; ks < 4; ks++) {
            uint32_t aH[4] = {pA_hi[2 * ks], pB_hi[2 * ks], pA_hi[2 * ks + 1], pB_hi[2 * ks + 1]};
            uint32_t aL[4] = {pA_lo[2 * ks], pB_lo[2 * ks], pA_lo[2 * ks + 1], pB_lo[2 * ks + 1]};
#pragma unroll
            for (int ng = 0; ng < 4; ng++) {
                uint32_t vfh[4], vfl[4];
                uint32_t off = (uint32_t)((ks * 16 + (lid & 15)) * KST + ng * 16 + ((lid >> 4) << 3)) * 2;
                ldm_x4_t(vfh, bV_h + off);
                ldm_x4_t(vfl, bV_l + off);
#pragma unroll
                for (int s = 0; s < 2; s++) {
                    float* d = O[ng * 2 + s];
                    mma_bf16(d, aH, vfh[s * 2], vfh[s * 2 + 1]);
                    mma_bf16(d, aH, vfl[s * 2], vfl[s * 2 + 1]);
                    mma_bf16(d, aL, vfh[s * 2], vfh[s * 2 + 1]);
                }
            }
        }
        __syncthreads();
    }

    // ---- epilogue: normalize, split to bf16 hi/lo, scatter to ctx [t][d]
    const float inv0 = 1.f / l0;
    const float inv1 = 1.f / l1;
    const int b = bh >> 4;
    const int h = bh & 15;
    const int sq = qt * 64 + wq * 16 + (lid >> 2);
#pragma unroll
    for (int ni = 0; ni < 8; ni++) {
        int col = h * 64 + ni * 8 + (lid & 3) * 2;
        uint32_t hi, lo;
        split2(O[ni][0] * inv0, O[ni][1] * inv0, hi, lo);
        size_t d0 = (size_t)(sq * BATCH + b) * DMODEL + col;
        *reinterpret_cast<uint32_t*>(ch + d0) = hi;
        *reinterpret_cast<uint32_t*>(cl + d0) = lo;
        split2(O[ni][2] * inv1, O[ni][3] * inv1, hi, lo);
        size_t d1 = (size_t)((sq + 8) * BATCH + b) * DMODEL + col;
        *reinterpret_cast<uint32_t*>(ch + d1) = hi;
        *reinterpret_cast<uint32_t*>(cl + d1) = lo;
    }
}

// ---------------------------------------------------------------------------
// Launch
// ---------------------------------------------------------------------------
extern "C" void kernel_launch(void* const* d_in, const int* in_sizes, int n_in,
                              void* d_out, int out_size)
{
    const float* query = (const float*)d_in[0];
    const float* q_w   = (const float*)d_in[1];
    const float* q_b   = (const float*)d_in[2];
    const float* k_w   = (const float*)d_in[3];
    const float* k_b   = (const float*)d_in[4];
    const float* v_w   = (const float*)d_in[5];
    const float* v_b   = (const float*)d_in[6];
    const float* out_w = (const float*)d_in[7];
    const float* out_b = (const float*)d_in[8];
    float* out = (float*)d_out;

    __nv_bfloat16 *xh, *xl, *ch, *cl;
    __nv_bfloat16 *qwh, *qwl, *kwh, *kwl, *vwh, *vwl, *owh, *owl;
    __nv_bfloat16 *qhp, *qlp, *khp, *klp, *vhp, *vlp;
    cudaGetSymbolAddress((void**)&xh, g_x_hi);
    cudaGetSymbolAddress((void**)&xl, g_x_lo);
    cudaGetSymbolAddress((void**)&ch, g_c_hi);
    cudaGetSymbolAddress((void**)&cl, g_c_lo);
    cudaGetSymbolAddress((void**)&qwh, g_qw_hi);
    cudaGetSymbolAddress((void**)&qwl, g_qw_lo);
    cudaGetSymbolAddress((void**)&kwh, g_kw_hi);
    cudaGetSymbolAddress((void**)&kwl, g_kw_lo);
    cudaGetSymbolAddress((void**)&vwh, g_vw_hi);
    cudaGetSymbolAddress((void**)&vwl, g_vw_lo);
    cudaGetSymbolAddress((void**)&owh, g_ow_hi);
    cudaGetSymbolAddress((void**)&owl, g_ow_lo);
    cudaGetSymbolAddress((void**)&qhp, g_qh);
    cudaGetSymbolAddress((void**)&qlp, g_ql);
    cudaGetSymbolAddress((void**)&khp, g_kh);
    cudaGetSymbolAddress((void**)&klp, g_kl);
    cudaGetSymbolAddress((void**)&vhp, g_vh);
    cudaGetSymbolAddress((void**)&vlp, g_vl);

    static bool attr_done = false;
    if (!attr_done) {
        cudaFuncSetAttribute(gemm_qkv, cudaFuncAttributeMaxDynamicSharedMemorySize, G_SMEM);
        cudaFuncSetAttribute(gemm_out, cudaFuncAttributeMaxDynamicSharedMemorySize, G_SMEM);
        cudaFuncSetAttribute(attn_mma, cudaFuncAttributeMaxDynamicSharedMemorySize, A_SMEM);
        attr_done = true;
    }

    const int nTok = MTOK * DMODEL;      // 4M
    const int nW   = DMODEL * DMODEL;    // 1M
    const float qscale = 0.125f;

    cvt_split<<<nTok / 1024, 256>>>(query, xh, xl, nTok, 1.0f);
    cvt_split<<<nW / 1024, 256>>>(q_w, qwh, qwl, nW, qscale);
    cvt_split<<<nW / 1024, 256>>>(k_w, kwh, kwl, nW, 1.0f);
    cvt_split<<<nW / 1024, 256>>>(v_w, vwh, vwl, nW, 1.0f);
    cvt_split<<<nW / 1024, 256>>>(out_w, owh, owl, nW, 1.0f);

    ProjSet pq = {qwh, qwl, q_b, qscale, qhp, qlp};
    ProjSet pk = {kwh, kwl, k_b, 1.0f,   khp, klp};
    ProjSet pv = {vwh, vwl, v_b, 1.0f,   vhp, vlp};

    dim3 gqkv(DMODEL / 128, MTOK / 128, 3);   // (8, 32, 3)
    gemm_qkv<<<gqkv, 256, G_SMEM>>>(xh, xl, pq, pk, pv, MTOK, DMODEL, DMODEL);

    dim3 gattn(SEQL / 64, NBH);               // (32, 32)
    attn_mma<<<gattn, 128, A_SMEM>>>(qhp, qlp, khp, klp, vhp, vlp, ch, cl);

    dim3 gout(DMODEL / 128, MTOK / 128);      // (8, 32)
    gemm_out<<<gout, 256, G_SMEM>>>(ch, cl, owh, owl, out_b, out, MTOK, DMODEL, DMODEL);
}